// round 1
// baseline (speedup 1.0000x reference)
#include <cuda_runtime.h>
#include <math.h>

// Problem constants (fixed by the dataset)
#define NNODES 50000
#define LDIM   4
#define DDIM   128
#define KDIM   16
#define EEDGES 800000
#define MROWS  (LDIM * NNODES)        // 200000, multiple of 64
#define ROWELTS ((size_t)MROWS * DDIM) // 25.6M floats
#define DECAYF 0.7f
#define EPSF   1e-5f

// ---------------- scratch (device globals; no allocation) ----------------
__device__ float g_proj[MROWS * DDIM];
__device__ float g_v   [MROWS * DDIM];
__device__ float g_agg [MROWS * DDIM];
__device__ float g_sage[MROWS * DDIM];
__device__ float g_att [MROWS * DDIM];
__device__ float g_h   [MROWS * DDIM];
__device__ float g_w0 [MROWS];
__device__ float g_it1[MROWS];
__device__ float g_it2[MROWS];

// ---------------- fused GEMM: C[M,128] = A[M, NCHUNK*128] @ B ----------------
// Tile: 64 rows x 128 cols per block, 256 threads.
// Thread (tx,ty): tx=lane (4 cols at tx*4), ty=warp (8 rows at ty*8).
// A warp owns 8 complete rows -> LayerNorm epilogue via warp shuffles.
// EPI: 0 = store raw, 1 = store acc+bias, 2 = LN(silu(acc + bias? + add?))*g+b
#define GEMM_SMEM ((64 * 128 + 128 * 128) * 4)

template <int NCHUNK, int EPI>
__global__ void __launch_bounds__(256, 2) gemm_kernel(
    const float* __restrict__ A0, const float* __restrict__ A1,
    const float* __restrict__ B,
    const float* __restrict__ bias, const float* __restrict__ addb,
    const float* __restrict__ lng, const float* __restrict__ lnb,
    float* __restrict__ C)
{
    extern __shared__ float smem[];
    float* As = smem;            // 64 x 128
    float* Bs = smem + 64 * 128; // 128 x 128

    const int tid = threadIdx.x;
    const int tx = tid & 31;
    const int ty = tid >> 5;
    const int blockRow = blockIdx.x * 64;

    float acc[8][4];
#pragma unroll
    for (int i = 0; i < 8; i++)
#pragma unroll
        for (int j = 0; j < 4; j++) acc[i][j] = 0.f;

#pragma unroll
    for (int ch = 0; ch < NCHUNK; ch++) {
        const float* A = (NCHUNK == 2 && ch == 1) ? A1 : A0;
        // A tile: 64 consecutive rows of 128 floats = 8192 contiguous floats
        const float4* Ag = (const float4*)(A + (size_t)blockRow * DDIM);
        float4* As4w = (float4*)As;
#pragma unroll
        for (int f = 0; f < 8; f++) As4w[tid + f * 256] = Ag[tid + f * 256];
        // B tile: 128x128
        const float4* Bg = (const float4*)(B + ch * DDIM * DDIM);
        float4* Bs4w = (float4*)Bs;
#pragma unroll
        for (int f = 0; f < 16; f++) Bs4w[tid + f * 256] = Bg[tid + f * 256];
        __syncthreads();

        const float4* As4 = (const float4*)As + ty * 8 * 32; // this warp's 8 rows
        const float4* Bs4 = (const float4*)Bs;
#pragma unroll 2
        for (int k4 = 0; k4 < 32; k4++) {
            float4 b0 = Bs4[(k4 * 4 + 0) * 32 + tx];
            float4 b1 = Bs4[(k4 * 4 + 1) * 32 + tx];
            float4 b2 = Bs4[(k4 * 4 + 2) * 32 + tx];
            float4 b3 = Bs4[(k4 * 4 + 3) * 32 + tx];
#pragma unroll
            for (int i = 0; i < 8; i++) {
                float4 a = As4[i * 32 + k4];
                acc[i][0] += a.x * b0.x; acc[i][1] += a.x * b0.y; acc[i][2] += a.x * b0.z; acc[i][3] += a.x * b0.w;
                acc[i][0] += a.y * b1.x; acc[i][1] += a.y * b1.y; acc[i][2] += a.y * b1.z; acc[i][3] += a.y * b1.w;
                acc[i][0] += a.z * b2.x; acc[i][1] += a.z * b2.y; acc[i][2] += a.z * b2.z; acc[i][3] += a.z * b2.w;
                acc[i][0] += a.w * b3.x; acc[i][1] += a.w * b3.y; acc[i][2] += a.w * b3.z; acc[i][3] += a.w * b3.w;
            }
        }
        __syncthreads();
    }

    // -------- epilogue --------
    float4 bias4 = make_float4(0.f, 0.f, 0.f, 0.f);
    if (EPI >= 1 && bias) bias4 = ((const float4*)bias)[tx];

    if constexpr (EPI == 2) {
        const float4 g4 = ((const float4*)lng)[tx];
        const float4 b4 = ((const float4*)lnb)[tx];
#pragma unroll
        for (int i = 0; i < 8; i++) {
            const size_t r = (size_t)blockRow + ty * 8 + i;
            float4 t = make_float4(acc[i][0] + bias4.x, acc[i][1] + bias4.y,
                                   acc[i][2] + bias4.z, acc[i][3] + bias4.w);
            if (addb) {
                float4 ad = ((const float4*)addb)[r * 32 + tx];
                t.x += ad.x; t.y += ad.y; t.z += ad.z; t.w += ad.w;
            }
            float4 s;
            s.x = t.x / (1.f + expf(-t.x));
            s.y = t.y / (1.f + expf(-t.y));
            s.z = t.z / (1.f + expf(-t.z));
            s.w = t.w / (1.f + expf(-t.w));
            float sum = s.x + s.y + s.z + s.w;
            float sq  = s.x * s.x + s.y * s.y + s.z * s.z + s.w * s.w;
#pragma unroll
            for (int off = 16; off; off >>= 1) {
                sum += __shfl_xor_sync(0xFFFFFFFFu, sum, off);
                sq  += __shfl_xor_sync(0xFFFFFFFFu, sq,  off);
            }
            const float mean = sum * (1.f / 128.f);
            const float var  = sq * (1.f / 128.f) - mean * mean;
            const float rstd = rsqrtf(var + EPSF);
            float4 o;
            o.x = (s.x - mean) * rstd * g4.x + b4.x;
            o.y = (s.y - mean) * rstd * g4.y + b4.y;
            o.z = (s.z - mean) * rstd * g4.z + b4.z;
            o.w = (s.w - mean) * rstd * g4.w + b4.w;
            ((float4*)C)[r * 32 + tx] = o;
        }
    } else {
#pragma unroll
        for (int i = 0; i < 8; i++) {
            const size_t r = (size_t)blockRow + ty * 8 + i;
            float4 o = make_float4(acc[i][0] + bias4.x, acc[i][1] + bias4.y,
                                   acc[i][2] + bias4.z, acc[i][3] + bias4.w);
            ((float4*)C)[r * 32 + tx] = o;
        }
    }
}

// ---------------- k/q retention weights: w0[r] = mean_j (x_r . Wk_j)(x_r . Wq_j) ----------------
__global__ void kq_kernel(const float* __restrict__ x,
                          const float* __restrict__ Wk, const float* __restrict__ Wq,
                          float* __restrict__ w0)
{
    __shared__ float4 sk4[KDIM * 32]; // transposed: [j][k/4] as float4
    __shared__ float4 sq4[KDIM * 32];
    float* sk = (float*)sk4;
    float* sqm = (float*)sq4;
    for (int idx = threadIdx.x; idx < DDIM * KDIM; idx += blockDim.x) {
        int k = idx >> 4, j = idx & 15; // Wk is [D][KD] row-major
        sk[j * DDIM + k] = Wk[idx];
        sqm[j * DDIM + k] = Wq[idx];
    }
    __syncthreads();

    const int lane = threadIdx.x & 31;
    int warp = (blockIdx.x * blockDim.x + threadIdx.x) >> 5;
    const int nwarps = (gridDim.x * blockDim.x) >> 5;

    for (size_t r = warp; r < (size_t)MROWS; r += nwarps) {
        const float4 xv = ((const float4*)x)[r * 32 + lane];
        float pk[KDIM], pq[KDIM];
#pragma unroll
        for (int j = 0; j < KDIM; j++) {
            float4 wk = sk4[j * 32 + lane];
            float4 wq = sq4[j * 32 + lane];
            pk[j] = xv.x * wk.x + xv.y * wk.y + xv.z * wk.z + xv.w * wk.w;
            pq[j] = xv.x * wq.x + xv.y * wq.y + xv.z * wq.z + xv.w * wq.w;
        }
#pragma unroll
        for (int off = 16; off; off >>= 1) {
#pragma unroll
            for (int j = 0; j < KDIM; j++) {
                pk[j] += __shfl_xor_sync(0xFFFFFFFFu, pk[j], off);
                pq[j] += __shfl_xor_sync(0xFFFFFFFFu, pq[j], off);
            }
        }
        if (lane == 0) {
            float s = 0.f;
#pragma unroll
            for (int j = 0; j < KDIM; j++) s += pk[j] * pq[j];
            w0[r] = s * (1.f / (float)KDIM);
        }
    }
}

// ---------------- main spmm: agg[l,row,:] += val * x[l,col,:]  (warp per edge) ----------------
__global__ void spmm_big(const int* __restrict__ ei, const float* __restrict__ ev,
                         const float* __restrict__ x, float* __restrict__ agg)
{
    const int gw = (blockIdx.x * blockDim.x + threadIdx.x) >> 5;
    const int lane = threadIdx.x & 31;
    if (gw >= EEDGES) return;
    const int row = ei[gw];
    const int col = ei[EEDGES + gw];
    const float val = ev[gw];
#pragma unroll
    for (int l = 0; l < LDIM; l++) {
        const float4 xv = ((const float4*)x)[((size_t)l * NNODES + col) * 32 + lane];
        float* dst = agg + ((size_t)l * NNODES + row) * DDIM + lane * 4;
        atomicAdd(dst + 0, val * xv.x);
        atomicAdd(dst + 1, val * xv.y);
        atomicAdd(dst + 2, val * xv.z);
        atomicAdd(dst + 3, val * xv.w);
    }
}

// ---------------- small spmm on [L,N] retention weights ----------------
__global__ void spmm_small(const int* __restrict__ ei, const float* __restrict__ ev,
                           const float* __restrict__ src, float* __restrict__ dst)
{
    const int e = blockIdx.x * blockDim.x + threadIdx.x;
    if (e >= EEDGES) return;
    const int row = ei[e];
    const int col = ei[EEDGES + e];
    const float v = DECAYF * ev[e];
#pragma unroll
    for (int l = 0; l < LDIM; l++)
        atomicAdd(&dst[l * NNODES + row], v * src[l * NNODES + col]);
}

// ---------------- attention output: att = LN(v * (w0+it1+it2)) ----------------
__global__ void att_ln_kernel(const float* __restrict__ v,
                              const float* __restrict__ w0, const float* __restrict__ it1,
                              const float* __restrict__ it2,
                              const float* __restrict__ g, const float* __restrict__ b,
                              float* __restrict__ out)
{
    const int lane = threadIdx.x & 31;
    int warp = (blockIdx.x * blockDim.x + threadIdx.x) >> 5;
    const int nwarps = (gridDim.x * blockDim.x) >> 5;
    const float4 g4 = ((const float4*)g)[lane];
    const float4 b4 = ((const float4*)b)[lane];

    for (size_t r = warp; r < (size_t)MROWS; r += nwarps) {
        const float w = w0[r] + it1[r] + it2[r];
        float4 s = ((const float4*)v)[r * 32 + lane];
        s.x *= w; s.y *= w; s.z *= w; s.w *= w;
        float sum = s.x + s.y + s.z + s.w;
        float sq  = s.x * s.x + s.y * s.y + s.z * s.z + s.w * s.w;
#pragma unroll
        for (int off = 16; off; off >>= 1) {
            sum += __shfl_xor_sync(0xFFFFFFFFu, sum, off);
            sq  += __shfl_xor_sync(0xFFFFFFFFu, sq,  off);
        }
        const float mean = sum * (1.f / 128.f);
        const float var  = sq * (1.f / 128.f) - mean * mean;
        const float rstd = rsqrtf(var + EPSF);
        float4 o;
        o.x = (s.x - mean) * rstd * g4.x + b4.x;
        o.y = (s.y - mean) * rstd * g4.y + b4.y;
        o.z = (s.z - mean) * rstd * g4.z + b4.z;
        o.w = (s.w - mean) * rstd * g4.w + b4.w;
        ((float4*)out)[r * 32 + lane] = o;
    }
}

// ---------------- host ----------------
extern "C" void kernel_launch(void* const* d_in, const int* in_sizes, int n_in,
                              void* d_out, int out_size)
{
    const float* x          = (const float*)d_in[0];
    const int*   ei         = (const int*)  d_in[1];
    const float* ev         = (const float*)d_in[2];
    const float* sage_W     = (const float*)d_in[3];
    const float* sage_b     = (const float*)d_in[4];
    const float* sage_aggW  = (const float*)d_in[5];
    const float* sage_ln_g  = (const float*)d_in[6];
    const float* sage_ln_b  = (const float*)d_in[7];
    const float* att_Wk     = (const float*)d_in[8];
    const float* att_Wq     = (const float*)d_in[9];
    const float* att_Wv     = (const float*)d_in[10];
    const float* att_ln_g   = (const float*)d_in[11];
    const float* att_ln_b   = (const float*)d_in[12];
    const float* lin1_W     = (const float*)d_in[13];
    const float* lin1_b     = (const float*)d_in[14];
    const float* lin2_W     = (const float*)d_in[15];
    const float* lin2_b     = (const float*)d_in[16];
    const float* ln1_g      = (const float*)d_in[17];
    const float* ln1_b      = (const float*)d_in[18];
    const float* ln2_g      = (const float*)d_in[19];
    const float* ln2_b      = (const float*)d_in[20];
    float* out = (float*)d_out;

    float *proj, *v, *agg, *sage, *att, *h, *w0, *it1, *it2;
    cudaGetSymbolAddress((void**)&proj, g_proj);
    cudaGetSymbolAddress((void**)&v,    g_v);
    cudaGetSymbolAddress((void**)&agg,  g_agg);
    cudaGetSymbolAddress((void**)&sage, g_sage);
    cudaGetSymbolAddress((void**)&att,  g_att);
    cudaGetSymbolAddress((void**)&h,    g_h);
    cudaGetSymbolAddress((void**)&w0,   g_w0);
    cudaGetSymbolAddress((void**)&it1,  g_it1);
    cudaGetSymbolAddress((void**)&it2,  g_it2);

    cudaFuncSetAttribute(gemm_kernel<1, 0>, cudaFuncAttributeMaxDynamicSharedMemorySize, GEMM_SMEM);
    cudaFuncSetAttribute(gemm_kernel<1, 1>, cudaFuncAttributeMaxDynamicSharedMemorySize, GEMM_SMEM);
    cudaFuncSetAttribute(gemm_kernel<1, 2>, cudaFuncAttributeMaxDynamicSharedMemorySize, GEMM_SMEM);
    cudaFuncSetAttribute(gemm_kernel<2, 2>, cudaFuncAttributeMaxDynamicSharedMemorySize, GEMM_SMEM);

    const int gemmGrid = MROWS / 64; // 3125

    // zero accumulation buffers
    cudaMemsetAsync(agg, 0, ROWELTS * sizeof(float), 0);
    cudaMemsetAsync(it1, 0, (size_t)MROWS * sizeof(float), 0);
    cudaMemsetAsync(it2, 0, (size_t)MROWS * sizeof(float), 0);

    // proj = x @ sage_W + sage_b ; v = x @ att_Wv
    gemm_kernel<1, 1><<<gemmGrid, 256, GEMM_SMEM>>>(x, nullptr, sage_W, sage_b, nullptr, nullptr, nullptr, proj);
    gemm_kernel<1, 0><<<gemmGrid, 256, GEMM_SMEM>>>(x, nullptr, att_Wv, nullptr, nullptr, nullptr, nullptr, v);

    // retention base weights
    kq_kernel<<<1480, 256>>>(x, att_Wk, att_Wq, w0);

    // graph aggregation (main spmm): 1 warp per edge
    spmm_big<<<(EEDGES * 32 + 255) / 256, 256>>>(ei, ev, x, agg);

    // retention iterations
    spmm_small<<<(EEDGES + 255) / 256, 256>>>(ei, ev, w0, it1);
    spmm_small<<<(EEDGES + 255) / 256, 256>>>(ei, ev, it1, it2);

    // sage_out = LN(silu(proj + agg @ aggW))
    gemm_kernel<1, 2><<<gemmGrid, 256, GEMM_SMEM>>>(agg, nullptr, sage_aggW, nullptr, proj,
                                                    sage_ln_g, sage_ln_b, sage);
    // att_out = LN(v * weights)
    att_ln_kernel<<<1480, 256>>>(v, w0, it1, it2, att_ln_g, att_ln_b, att);

    // h = LN(silu(concat(sage,att) @ lin1_W + lin1_b))
    gemm_kernel<2, 2><<<gemmGrid, 256, GEMM_SMEM>>>(sage, att, lin1_W, lin1_b, nullptr,
                                                    ln1_g, ln1_b, h);
    // out = LN(silu(h @ lin2_W + lin2_b + x))
    gemm_kernel<1, 2><<<gemmGrid, 256, GEMM_SMEM>>>(h, nullptr, lin2_W, lin2_b, x,
                                                    ln2_g, ln2_b, out);
}

// round 2
// speedup vs baseline: 1.4947x; 1.4947x over previous
#include <cuda_runtime.h>
#include <math.h>

// Problem constants (fixed by the dataset)
#define NNODES 50000
#define LDIM   4
#define DDIM   128
#define KDIM   16
#define EEDGES 800000
#define MROWS  (LDIM * NNODES)        // 200000, multiple of 64
#define ROWELTS ((size_t)MROWS * DDIM) // 25.6M floats
#define DECAYF 0.7f
#define EPSF   1e-5f

// ---------------- scratch (device globals; no allocation) ----------------
__device__ float g_proj[MROWS * DDIM];
__device__ float g_v   [MROWS * DDIM];
__device__ float g_agg [MROWS * DDIM];
__device__ float g_sage[MROWS * DDIM];
__device__ float g_att [MROWS * DDIM];
__device__ float g_h   [MROWS * DDIM];
__device__ float g_w0 [MROWS];
__device__ float g_it1[MROWS];
__device__ float g_it2[MROWS];

// CSR build scratch
__device__ int   g_cnt[NNODES];
__device__ int   g_cur[NNODES];
__device__ int   g_rowstart[NNODES + 1];
__device__ int   g_ecol[EEDGES];
__device__ float g_eval[EEDGES];

// ================= CSR construction =================
__global__ void hist_kernel(const int* __restrict__ ei, int* __restrict__ cnt)
{
    int e = blockIdx.x * blockDim.x + threadIdx.x;
    if (e < EEDGES) atomicAdd(&cnt[ei[e]], 1);
}

// single-block exclusive scan over NNODES counters
__global__ void scan_kernel(const int* __restrict__ cnt, int* __restrict__ rowstart)
{
    const int T = 1024;
    __shared__ int partial[T];
    const int tid = threadIdx.x;
    const int chunk = (NNODES + T - 1) / T; // 49
    const int base = tid * chunk;
    int s = 0;
    for (int i = 0; i < chunk; i++) {
        int idx = base + i;
        if (idx < NNODES) s += cnt[idx];
    }
    partial[tid] = s;
    __syncthreads();
    // Hillis-Steele inclusive scan
    for (int off = 1; off < T; off <<= 1) {
        int v = (tid >= off) ? partial[tid - off] : 0;
        __syncthreads();
        partial[tid] += v;
        __syncthreads();
    }
    int run = (tid == 0) ? 0 : partial[tid - 1];
    for (int i = 0; i < chunk; i++) {
        int idx = base + i;
        if (idx < NNODES) { rowstart[idx] = run; run += cnt[idx]; }
    }
    if (tid == T - 1) rowstart[NNODES] = run;
}

__global__ void scatter_kernel(const int* __restrict__ ei, const float* __restrict__ ev,
                               const int* __restrict__ rowstart, int* __restrict__ cur,
                               int* __restrict__ ecol, float* __restrict__ eval_)
{
    int e = blockIdx.x * blockDim.x + threadIdx.x;
    if (e >= EEDGES) return;
    const int r = ei[e];
    const int pos = rowstart[r] + atomicAdd(&cur[r], 1);
    ecol[pos]  = ei[EEDGES + e];
    eval_[pos] = ev[e];
}

// ================= gather spmm (no atomics) =================
// one warp per (row, l); lanes own 4 columns each; registers accumulate
__global__ void __launch_bounds__(256) spmm_gather(
    const int* __restrict__ rowstart,
    const int* __restrict__ ecol, const float* __restrict__ eval_,
    const float* __restrict__ x, float* __restrict__ agg)
{
    const int gw = (blockIdx.x * blockDim.x + threadIdx.x) >> 5;
    const int lane = threadIdx.x & 31;
    const int row = gw >> 2;
    const int l   = gw & 3;
    if (row >= NNODES) return;

    const int s = rowstart[row];
    const int e = rowstart[row + 1];
    const float4* xl = (const float4*)x + (size_t)l * NNODES * 32;

    float4 acc = make_float4(0.f, 0.f, 0.f, 0.f);
    int i = s;
    // unroll-by-2 for MLP
    for (; i + 2 <= e; i += 2) {
        const int   c0 = ecol[i],     c1 = ecol[i + 1];
        const float v0 = eval_[i],    v1 = eval_[i + 1];
        float4 x0 = xl[(size_t)c0 * 32 + lane];
        float4 x1 = xl[(size_t)c1 * 32 + lane];
        acc.x += v0 * x0.x; acc.y += v0 * x0.y; acc.z += v0 * x0.z; acc.w += v0 * x0.w;
        acc.x += v1 * x1.x; acc.y += v1 * x1.y; acc.z += v1 * x1.z; acc.w += v1 * x1.w;
    }
    if (i < e) {
        const int c0 = ecol[i];
        const float v0 = eval_[i];
        float4 x0 = xl[(size_t)c0 * 32 + lane];
        acc.x += v0 * x0.x; acc.y += v0 * x0.y; acc.z += v0 * x0.z; acc.w += v0 * x0.w;
    }
    ((float4*)agg)[((size_t)l * NNODES + row) * 32 + lane] = acc;
}

// ================= retention spmm on [L,N] weights (gather) =================
// one warp per row; lanes stride edges; 4 accumulators (one per l)
__global__ void __launch_bounds__(256) ret_gather(
    const int* __restrict__ rowstart,
    const int* __restrict__ ecol, const float* __restrict__ eval_,
    const float* __restrict__ src, float* __restrict__ dst)
{
    const int row = (blockIdx.x * blockDim.x + threadIdx.x) >> 5;
    const int lane = threadIdx.x & 31;
    if (row >= NNODES) return;
    const int s = rowstart[row];
    const int e = rowstart[row + 1];

    float a0 = 0.f, a1 = 0.f, a2 = 0.f, a3 = 0.f;
    for (int i = s + lane; i < e; i += 32) {
        const int c = ecol[i];
        const float v = DECAYF * eval_[i];
        a0 += v * src[c];
        a1 += v * src[NNODES + c];
        a2 += v * src[2 * NNODES + c];
        a3 += v * src[3 * NNODES + c];
    }
#pragma unroll
    for (int off = 16; off; off >>= 1) {
        a0 += __shfl_xor_sync(0xFFFFFFFFu, a0, off);
        a1 += __shfl_xor_sync(0xFFFFFFFFu, a1, off);
        a2 += __shfl_xor_sync(0xFFFFFFFFu, a2, off);
        a3 += __shfl_xor_sync(0xFFFFFFFFu, a3, off);
    }
    if (lane == 0) {
        dst[row]              = a0;
        dst[NNODES + row]     = a1;
        dst[2 * NNODES + row] = a2;
        dst[3 * NNODES + row] = a3;
    }
}

// ---------------- fused GEMM: C[M,128] = A[M, NCHUNK*128] @ B ----------------
#define GEMM_SMEM ((64 * 128 + 128 * 128) * 4)

template <int NCHUNK, int EPI>
__global__ void __launch_bounds__(256, 2) gemm_kernel(
    const float* __restrict__ A0, const float* __restrict__ A1,
    const float* __restrict__ B,
    const float* __restrict__ bias, const float* __restrict__ addb,
    const float* __restrict__ lng, const float* __restrict__ lnb,
    float* __restrict__ C)
{
    extern __shared__ float smem[];
    float* As = smem;            // 64 x 128
    float* Bs = smem + 64 * 128; // 128 x 128

    const int tid = threadIdx.x;
    const int tx = tid & 31;
    const int ty = tid >> 5;
    const int blockRow = blockIdx.x * 64;

    float acc[8][4];
#pragma unroll
    for (int i = 0; i < 8; i++)
#pragma unroll
        for (int j = 0; j < 4; j++) acc[i][j] = 0.f;

#pragma unroll
    for (int ch = 0; ch < NCHUNK; ch++) {
        const float* A = (NCHUNK == 2 && ch == 1) ? A1 : A0;
        const float4* Ag = (const float4*)(A + (size_t)blockRow * DDIM);
        float4* As4w = (float4*)As;
#pragma unroll
        for (int f = 0; f < 8; f++) As4w[tid + f * 256] = Ag[tid + f * 256];
        const float4* Bg = (const float4*)(B + ch * DDIM * DDIM);
        float4* Bs4w = (float4*)Bs;
#pragma unroll
        for (int f = 0; f < 16; f++) Bs4w[tid + f * 256] = Bg[tid + f * 256];
        __syncthreads();

        const float4* As4 = (const float4*)As + ty * 8 * 32;
        const float4* Bs4 = (const float4*)Bs;
#pragma unroll 2
        for (int k4 = 0; k4 < 32; k4++) {
            float4 b0 = Bs4[(k4 * 4 + 0) * 32 + tx];
            float4 b1 = Bs4[(k4 * 4 + 1) * 32 + tx];
            float4 b2 = Bs4[(k4 * 4 + 2) * 32 + tx];
            float4 b3 = Bs4[(k4 * 4 + 3) * 32 + tx];
#pragma unroll
            for (int i = 0; i < 8; i++) {
                float4 a = As4[i * 32 + k4];
                acc[i][0] += a.x * b0.x; acc[i][1] += a.x * b0.y; acc[i][2] += a.x * b0.z; acc[i][3] += a.x * b0.w;
                acc[i][0] += a.y * b1.x; acc[i][1] += a.y * b1.y; acc[i][2] += a.y * b1.z; acc[i][3] += a.y * b1.w;
                acc[i][0] += a.z * b2.x; acc[i][1] += a.z * b2.y; acc[i][2] += a.z * b2.z; acc[i][3] += a.z * b2.w;
                acc[i][0] += a.w * b3.x; acc[i][1] += a.w * b3.y; acc[i][2] += a.w * b3.z; acc[i][3] += a.w * b3.w;
            }
        }
        __syncthreads();
    }

    float4 bias4 = make_float4(0.f, 0.f, 0.f, 0.f);
    if (EPI >= 1 && bias) bias4 = ((const float4*)bias)[tx];

    if constexpr (EPI == 2) {
        const float4 g4 = ((const float4*)lng)[tx];
        const float4 b4 = ((const float4*)lnb)[tx];
#pragma unroll
        for (int i = 0; i < 8; i++) {
            const size_t r = (size_t)blockRow + ty * 8 + i;
            float4 t = make_float4(acc[i][0] + bias4.x, acc[i][1] + bias4.y,
                                   acc[i][2] + bias4.z, acc[i][3] + bias4.w);
            if (addb) {
                float4 ad = ((const float4*)addb)[r * 32 + tx];
                t.x += ad.x; t.y += ad.y; t.z += ad.z; t.w += ad.w;
            }
            float4 s;
            s.x = t.x / (1.f + expf(-t.x));
            s.y = t.y / (1.f + expf(-t.y));
            s.z = t.z / (1.f + expf(-t.z));
            s.w = t.w / (1.f + expf(-t.w));
            float sum = s.x + s.y + s.z + s.w;
            float sq  = s.x * s.x + s.y * s.y + s.z * s.z + s.w * s.w;
#pragma unroll
            for (int off = 16; off; off >>= 1) {
                sum += __shfl_xor_sync(0xFFFFFFFFu, sum, off);
                sq  += __shfl_xor_sync(0xFFFFFFFFu, sq,  off);
            }
            const float mean = sum * (1.f / 128.f);
            const float var  = sq * (1.f / 128.f) - mean * mean;
            const float rstd = rsqrtf(var + EPSF);
            float4 o;
            o.x = (s.x - mean) * rstd * g4.x + b4.x;
            o.y = (s.y - mean) * rstd * g4.y + b4.y;
            o.z = (s.z - mean) * rstd * g4.z + b4.z;
            o.w = (s.w - mean) * rstd * g4.w + b4.w;
            ((float4*)C)[r * 32 + tx] = o;
        }
    } else {
#pragma unroll
        for (int i = 0; i < 8; i++) {
            const size_t r = (size_t)blockRow + ty * 8 + i;
            float4 o = make_float4(acc[i][0] + bias4.x, acc[i][1] + bias4.y,
                                   acc[i][2] + bias4.z, acc[i][3] + bias4.w);
            ((float4*)C)[r * 32 + tx] = o;
        }
    }
}

// ---------------- k/q retention weights ----------------
__global__ void kq_kernel(const float* __restrict__ x,
                          const float* __restrict__ Wk, const float* __restrict__ Wq,
                          float* __restrict__ w0)
{
    __shared__ float4 sk4[KDIM * 32];
    __shared__ float4 sq4[KDIM * 32];
    float* sk = (float*)sk4;
    float* sqm = (float*)sq4;
    for (int idx = threadIdx.x; idx < DDIM * KDIM; idx += blockDim.x) {
        int k = idx >> 4, j = idx & 15;
        sk[j * DDIM + k] = Wk[idx];
        sqm[j * DDIM + k] = Wq[idx];
    }
    __syncthreads();

    const int lane = threadIdx.x & 31;
    int warp = (blockIdx.x * blockDim.x + threadIdx.x) >> 5;
    const int nwarps = (gridDim.x * blockDim.x) >> 5;

    for (size_t r = warp; r < (size_t)MROWS; r += nwarps) {
        const float4 xv = ((const float4*)x)[r * 32 + lane];
        float pk[KDIM], pq[KDIM];
#pragma unroll
        for (int j = 0; j < KDIM; j++) {
            float4 wk = sk4[j * 32 + lane];
            float4 wq = sq4[j * 32 + lane];
            pk[j] = xv.x * wk.x + xv.y * wk.y + xv.z * wk.z + xv.w * wk.w;
            pq[j] = xv.x * wq.x + xv.y * wq.y + xv.z * wq.z + xv.w * wq.w;
        }
#pragma unroll
        for (int off = 16; off; off >>= 1) {
#pragma unroll
            for (int j = 0; j < KDIM; j++) {
                pk[j] += __shfl_xor_sync(0xFFFFFFFFu, pk[j], off);
                pq[j] += __shfl_xor_sync(0xFFFFFFFFu, pq[j], off);
            }
        }
        if (lane == 0) {
            float s = 0.f;
#pragma unroll
            for (int j = 0; j < KDIM; j++) s += pk[j] * pq[j];
            w0[r] = s * (1.f / (float)KDIM);
        }
    }
}

// ---------------- attention output: att = LN(v * (w0+it1+it2)) ----------------
__global__ void att_ln_kernel(const float* __restrict__ v,
                              const float* __restrict__ w0, const float* __restrict__ it1,
                              const float* __restrict__ it2,
                              const float* __restrict__ g, const float* __restrict__ b,
                              float* __restrict__ out)
{
    const int lane = threadIdx.x & 31;
    int warp = (blockIdx.x * blockDim.x + threadIdx.x) >> 5;
    const int nwarps = (gridDim.x * blockDim.x) >> 5;
    const float4 g4 = ((const float4*)g)[lane];
    const float4 b4 = ((const float4*)b)[lane];

    for (size_t r = warp; r < (size_t)MROWS; r += nwarps) {
        const float w = w0[r] + it1[r] + it2[r];
        float4 s = ((const float4*)v)[r * 32 + lane];
        s.x *= w; s.y *= w; s.z *= w; s.w *= w;
        float sum = s.x + s.y + s.z + s.w;
        float sq  = s.x * s.x + s.y * s.y + s.z * s.z + s.w * s.w;
#pragma unroll
        for (int off = 16; off; off >>= 1) {
            sum += __shfl_xor_sync(0xFFFFFFFFu, sum, off);
            sq  += __shfl_xor_sync(0xFFFFFFFFu, sq,  off);
        }
        const float mean = sum * (1.f / 128.f);
        const float var  = sq * (1.f / 128.f) - mean * mean;
        const float rstd = rsqrtf(var + EPSF);
        float4 o;
        o.x = (s.x - mean) * rstd * g4.x + b4.x;
        o.y = (s.y - mean) * rstd * g4.y + b4.y;
        o.z = (s.z - mean) * rstd * g4.z + b4.z;
        o.w = (s.w - mean) * rstd * g4.w + b4.w;
        ((float4*)out)[r * 32 + lane] = o;
    }
}

// ---------------- host ----------------
extern "C" void kernel_launch(void* const* d_in, const int* in_sizes, int n_in,
                              void* d_out, int out_size)
{
    const float* x          = (const float*)d_in[0];
    const int*   ei         = (const int*)  d_in[1];
    const float* ev         = (const float*)d_in[2];
    const float* sage_W     = (const float*)d_in[3];
    const float* sage_b     = (const float*)d_in[4];
    const float* sage_aggW  = (const float*)d_in[5];
    const float* sage_ln_g  = (const float*)d_in[6];
    const float* sage_ln_b  = (const float*)d_in[7];
    const float* att_Wk     = (const float*)d_in[8];
    const float* att_Wq     = (const float*)d_in[9];
    const float* att_Wv     = (const float*)d_in[10];
    const float* att_ln_g   = (const float*)d_in[11];
    const float* att_ln_b   = (const float*)d_in[12];
    const float* lin1_W     = (const float*)d_in[13];
    const float* lin1_b     = (const float*)d_in[14];
    const float* lin2_W     = (const float*)d_in[15];
    const float* lin2_b     = (const float*)d_in[16];
    const float* ln1_g      = (const float*)d_in[17];
    const float* ln1_b      = (const float*)d_in[18];
    const float* ln2_g      = (const float*)d_in[19];
    const float* ln2_b      = (const float*)d_in[20];
    float* out = (float*)d_out;

    float *proj, *v, *agg, *sage, *att, *h, *w0, *it1, *it2;
    cudaGetSymbolAddress((void**)&proj, g_proj);
    cudaGetSymbolAddress((void**)&v,    g_v);
    cudaGetSymbolAddress((void**)&agg,  g_agg);
    cudaGetSymbolAddress((void**)&sage, g_sage);
    cudaGetSymbolAddress((void**)&att,  g_att);
    cudaGetSymbolAddress((void**)&h,    g_h);
    cudaGetSymbolAddress((void**)&w0,   g_w0);
    cudaGetSymbolAddress((void**)&it1,  g_it1);
    cudaGetSymbolAddress((void**)&it2,  g_it2);

    int *cnt, *cur, *rowstart, *ecol;
    float *eval_;
    cudaGetSymbolAddress((void**)&cnt,      g_cnt);
    cudaGetSymbolAddress((void**)&cur,      g_cur);
    cudaGetSymbolAddress((void**)&rowstart, g_rowstart);
    cudaGetSymbolAddress((void**)&ecol,     g_ecol);
    cudaGetSymbolAddress((void**)&eval_,    g_eval);

    cudaFuncSetAttribute(gemm_kernel<1, 0>, cudaFuncAttributeMaxDynamicSharedMemorySize, GEMM_SMEM);
    cudaFuncSetAttribute(gemm_kernel<1, 1>, cudaFuncAttributeMaxDynamicSharedMemorySize, GEMM_SMEM);
    cudaFuncSetAttribute(gemm_kernel<1, 2>, cudaFuncAttributeMaxDynamicSharedMemorySize, GEMM_SMEM);
    cudaFuncSetAttribute(gemm_kernel<2, 2>, cudaFuncAttributeMaxDynamicSharedMemorySize, GEMM_SMEM);

    const int gemmGrid = MROWS / 64; // 3125

    // ---- CSR build (replaces all atomics in the spmm path) ----
    cudaMemsetAsync(cnt, 0, NNODES * sizeof(int), 0);
    cudaMemsetAsync(cur, 0, NNODES * sizeof(int), 0);
    hist_kernel<<<(EEDGES + 255) / 256, 256>>>(ei, cnt);
    scan_kernel<<<1, 1024>>>(cnt, rowstart);
    scatter_kernel<<<(EEDGES + 255) / 256, 256>>>(ei, ev, rowstart, cur, ecol, eval_);

    // proj = x @ sage_W + sage_b ; v = x @ att_Wv
    gemm_kernel<1, 1><<<gemmGrid, 256, GEMM_SMEM>>>(x, nullptr, sage_W, sage_b, nullptr, nullptr, nullptr, proj);
    gemm_kernel<1, 0><<<gemmGrid, 256, GEMM_SMEM>>>(x, nullptr, att_Wv, nullptr, nullptr, nullptr, nullptr, v);

    // retention base weights
    kq_kernel<<<1480, 256>>>(x, att_Wk, att_Wq, w0);

    // graph aggregation: pure gather, warp per (row, l)
    spmm_gather<<<(NNODES * 4 * 32 + 255) / 256, 256>>>(rowstart, ecol, eval_, x, agg);

    // retention iterations: gather, warp per row
    ret_gather<<<(NNODES * 32 + 255) / 256, 256>>>(rowstart, ecol, eval_, w0, it1);
    ret_gather<<<(NNODES * 32 + 255) / 256, 256>>>(rowstart, ecol, eval_, it1, it2);

    // sage_out = LN(silu(proj + agg @ aggW))
    gemm_kernel<1, 2><<<gemmGrid, 256, GEMM_SMEM>>>(agg, nullptr, sage_aggW, nullptr, proj,
                                                    sage_ln_g, sage_ln_b, sage);
    // att_out = LN(v * weights)
    att_ln_kernel<<<1480, 256>>>(v, w0, it1, it2, att_ln_g, att_ln_b, att);

    // h = LN(silu(concat(sage,att) @ lin1_W + lin1_b))
    gemm_kernel<2, 2><<<gemmGrid, 256, GEMM_SMEM>>>(sage, att, lin1_W, lin1_b, nullptr,
                                                    ln1_g, ln1_b, h);
    // out = LN(silu(h @ lin2_W + lin2_b + x))
    gemm_kernel<1, 2><<<gemmGrid, 256, GEMM_SMEM>>>(h, nullptr, lin2_W, lin2_b, x,
                                                    ln2_g, ln2_b, out);
}

// round 3
// speedup vs baseline: 1.9375x; 1.2962x over previous
#include <cuda_runtime.h>
#include <math.h>

// Problem constants (fixed by the dataset)
#define NNODES 50000
#define LDIM   4
#define DDIM   128
#define KDIM   16
#define EEDGES 800000
#define MROWS  (LDIM * NNODES)        // 200000, multiple of 64
#define ROWELTS ((size_t)MROWS * DDIM)
#define DECAYF 0.7f
#define EPSF   1e-5f

// ---------------- scratch (device globals; no allocation) ----------------
__device__ float g_proj[MROWS * DDIM];
__device__ float g_v   [MROWS * DDIM];
__device__ float g_agg [MROWS * DDIM];
__device__ float g_sage[MROWS * DDIM];
__device__ float g_att [MROWS * DDIM];
__device__ float g_h   [MROWS * DDIM];
__device__ float g_w0 [MROWS];
__device__ float g_it1[MROWS];
__device__ float g_it2[MROWS];

// CSR build scratch
__device__ int   g_cnt[NNODES];
__device__ int   g_cur[NNODES];
__device__ int   g_rowstart[NNODES + 1];
__device__ int   g_ecol[EEDGES];
__device__ float g_eval[EEDGES];

// ================= CSR construction =================
__global__ void hist_kernel(const int* __restrict__ ei, int* __restrict__ cnt)
{
    int e = blockIdx.x * blockDim.x + threadIdx.x;
    if (e < EEDGES) atomicAdd(&cnt[ei[e]], 1);
}

__global__ void scan_kernel(const int* __restrict__ cnt, int* __restrict__ rowstart)
{
    const int T = 1024;
    __shared__ int partial[T];
    const int tid = threadIdx.x;
    const int chunk = (NNODES + T - 1) / T;
    const int base = tid * chunk;
    int s = 0;
    for (int i = 0; i < chunk; i++) {
        int idx = base + i;
        if (idx < NNODES) s += cnt[idx];
    }
    partial[tid] = s;
    __syncthreads();
    for (int off = 1; off < T; off <<= 1) {
        int v = (tid >= off) ? partial[tid - off] : 0;
        __syncthreads();
        partial[tid] += v;
        __syncthreads();
    }
    int run = (tid == 0) ? 0 : partial[tid - 1];
    for (int i = 0; i < chunk; i++) {
        int idx = base + i;
        if (idx < NNODES) { rowstart[idx] = run; run += cnt[idx]; }
    }
    if (tid == T - 1) rowstart[NNODES] = run;
}

__global__ void scatter_kernel(const int* __restrict__ ei, const float* __restrict__ ev,
                               const int* __restrict__ rowstart, int* __restrict__ cur,
                               int* __restrict__ ecol, float* __restrict__ eval_)
{
    int e = blockIdx.x * blockDim.x + threadIdx.x;
    if (e >= EEDGES) return;
    const int r = ei[e];
    const int pos = rowstart[r] + atomicAdd(&cur[r], 1);
    ecol[pos]  = ei[EEDGES + e];
    eval_[pos] = ev[e];
}

// ================= gather spmm (no atomics) =================
__global__ void __launch_bounds__(256) spmm_gather(
    const int* __restrict__ rowstart,
    const int* __restrict__ ecol, const float* __restrict__ eval_,
    const float* __restrict__ x, float* __restrict__ agg)
{
    const int gw = (blockIdx.x * blockDim.x + threadIdx.x) >> 5;
    const int lane = threadIdx.x & 31;
    const int row = gw >> 2;
    const int l   = gw & 3;
    if (row >= NNODES) return;

    const int s = rowstart[row];
    const int e = rowstart[row + 1];
    const float4* xl = (const float4*)x + (size_t)l * NNODES * 32;

    float4 acc = make_float4(0.f, 0.f, 0.f, 0.f);
    int i = s;
    for (; i + 2 <= e; i += 2) {
        const int   c0 = ecol[i],     c1 = ecol[i + 1];
        const float v0 = eval_[i],    v1 = eval_[i + 1];
        float4 x0 = xl[(size_t)c0 * 32 + lane];
        float4 x1 = xl[(size_t)c1 * 32 + lane];
        acc.x += v0 * x0.x; acc.y += v0 * x0.y; acc.z += v0 * x0.z; acc.w += v0 * x0.w;
        acc.x += v1 * x1.x; acc.y += v1 * x1.y; acc.z += v1 * x1.z; acc.w += v1 * x1.w;
    }
    if (i < e) {
        const int c0 = ecol[i];
        const float v0 = eval_[i];
        float4 x0 = xl[(size_t)c0 * 32 + lane];
        acc.x += v0 * x0.x; acc.y += v0 * x0.y; acc.z += v0 * x0.z; acc.w += v0 * x0.w;
    }
    ((float4*)agg)[((size_t)l * NNODES + row) * 32 + lane] = acc;
}

// ================= retention spmm on [L,N] weights (gather) =================
__global__ void __launch_bounds__(256) ret_gather(
    const int* __restrict__ rowstart,
    const int* __restrict__ ecol, const float* __restrict__ eval_,
    const float* __restrict__ src, float* __restrict__ dst)
{
    const int row = (blockIdx.x * blockDim.x + threadIdx.x) >> 5;
    const int lane = threadIdx.x & 31;
    if (row >= NNODES) return;
    const int s = rowstart[row];
    const int e = rowstart[row + 1];

    float a0 = 0.f, a1 = 0.f, a2 = 0.f, a3 = 0.f;
    for (int i = s + lane; i < e; i += 32) {
        const int c = ecol[i];
        const float v = DECAYF * eval_[i];
        a0 += v * src[c];
        a1 += v * src[NNODES + c];
        a2 += v * src[2 * NNODES + c];
        a3 += v * src[3 * NNODES + c];
    }
#pragma unroll
    for (int off = 16; off; off >>= 1) {
        a0 += __shfl_xor_sync(0xFFFFFFFFu, a0, off);
        a1 += __shfl_xor_sync(0xFFFFFFFFu, a1, off);
        a2 += __shfl_xor_sync(0xFFFFFFFFu, a2, off);
        a3 += __shfl_xor_sync(0xFFFFFFFFu, a3, off);
    }
    if (lane == 0) {
        dst[row]              = a0;
        dst[NNODES + row]     = a1;
        dst[2 * NNODES + row] = a2;
        dst[3 * NNODES + row] = a3;
    }
}

// ================= tf32 tensor-core GEMM =================
// C[M,128] = A[M, NCHUNK*128] @ B, fused epilogue.
// Block: 64 rows x 128 cols, 8 warps. Warp (wr,wc): rows wr*16..+15, cols wc*64..+63.
// mma.sync m16n8k8 tf32, fp32 accumulate. Acc staged through smem for LN epilogue.
#define AST 132
#define BST 132
#define GEMM_SMEM ((64 * AST + 128 * BST) * 4)   // 101376 bytes

__device__ __forceinline__ unsigned f2tf(float f)
{
    unsigned u;
    asm("cvt.rna.tf32.f32 %0, %1;" : "=r"(u) : "f"(f));
    return u;
}

__device__ __forceinline__ void mma8(float* c, const unsigned* a, unsigned b0, unsigned b1)
{
    asm volatile(
        "mma.sync.aligned.m16n8k8.row.col.f32.tf32.tf32.f32 "
        "{%0,%1,%2,%3},{%4,%5,%6,%7},{%8,%9},{%0,%1,%2,%3};"
        : "+f"(c[0]), "+f"(c[1]), "+f"(c[2]), "+f"(c[3])
        : "r"(a[0]), "r"(a[1]), "r"(a[2]), "r"(a[3]), "r"(b0), "r"(b1));
}

template <int NCHUNK, int EPI>
__global__ void __launch_bounds__(256, 2) gemm_tc(
    const float* __restrict__ A0, const float* __restrict__ A1,
    const float* __restrict__ B,
    const float* __restrict__ bias, const float* __restrict__ addb,
    const float* __restrict__ lng, const float* __restrict__ lnb,
    float* __restrict__ C)
{
    extern __shared__ unsigned smem_u[];
    unsigned* As = smem_u;            // 64 x AST tf32
    unsigned* Bs = smem_u + 64 * AST; // 128 x BST tf32
    float* Cs = (float*)smem_u;       // reuse As region for epilogue (64 x AST floats)

    const int tid  = threadIdx.x;
    const int lane = tid & 31;
    const int wid  = tid >> 5;
    const int wr   = wid & 3;
    const int wc   = wid >> 2;
    const int tg   = lane & 3;   // threadID in group
    const int gr   = lane >> 2;  // group ID
    const int blockRow = blockIdx.x * 64;

    float acc[8][4];
#pragma unroll
    for (int i = 0; i < 8; i++)
#pragma unroll
        for (int j = 0; j < 4; j++) acc[i][j] = 0.f;

#pragma unroll
    for (int ch = 0; ch < NCHUNK; ch++) {
        const float* A = (NCHUNK == 2 && ch == 1) ? A1 : A0;
        // A tile: 64x128 -> As padded
        const float4* Ag = (const float4*)(A + (size_t)blockRow * DDIM);
#pragma unroll
        for (int f = 0; f < 8; f++) {
            int i4 = tid + f * 256;
            float4 v = Ag[i4];
            int e = i4 * 4;
            unsigned* dst = As + (e >> 7) * AST + (e & 127);
            dst[0] = f2tf(v.x); dst[1] = f2tf(v.y); dst[2] = f2tf(v.z); dst[3] = f2tf(v.w);
        }
        // B tile: 128x128 -> Bs padded ([k][n])
        const float4* Bg = (const float4*)(B + ch * DDIM * DDIM);
#pragma unroll
        for (int f = 0; f < 16; f++) {
            int i4 = tid + f * 256;
            float4 v = Bg[i4];
            int e = i4 * 4;
            unsigned* dst = Bs + (e >> 7) * BST + (e & 127);
            dst[0] = f2tf(v.x); dst[1] = f2tf(v.y); dst[2] = f2tf(v.z); dst[3] = f2tf(v.w);
        }
        __syncthreads();

        const unsigned* Abase = As + (wr * 16 + gr) * AST + tg;
#pragma unroll
        for (int k8 = 0; k8 < 16; k8++) {
            const int k0 = k8 * 8;
            unsigned a[4];
            a[0] = Abase[k0];
            a[1] = Abase[8 * AST + k0];
            a[2] = Abase[k0 + 4];
            a[3] = Abase[8 * AST + k0 + 4];
            const unsigned* Bb = Bs + (k0 + tg) * BST + wc * 64 + gr;
#pragma unroll
            for (int nt = 0; nt < 8; nt++) {
                unsigned b0 = Bb[nt * 8];
                unsigned b1 = Bb[4 * BST + nt * 8];
                mma8(acc[nt], a, b0, b1);
            }
        }
        __syncthreads();
    }

    // stage acc into smem (row-major 64 x AST floats)
    {
        const int r0 = wr * 16 + gr;
#pragma unroll
        for (int nt = 0; nt < 8; nt++) {
            const int c = wc * 64 + nt * 8 + 2 * tg;
            Cs[r0 * AST + c]           = acc[nt][0];
            Cs[r0 * AST + c + 1]       = acc[nt][1];
            Cs[(r0 + 8) * AST + c]     = acc[nt][2];
            Cs[(r0 + 8) * AST + c + 1] = acc[nt][3];
        }
    }
    __syncthreads();

    // epilogue: warp wid owns rows wid*8..+7; lane owns 4 cols at lane*4
    float4 bias4 = make_float4(0.f, 0.f, 0.f, 0.f);
    if (EPI >= 1 && bias) bias4 = ((const float4*)bias)[lane];

    if constexpr (EPI == 2) {
        const float4 g4 = ((const float4*)lng)[lane];
        const float4 b4 = ((const float4*)lnb)[lane];
#pragma unroll
        for (int i = 0; i < 8; i++) {
            const int r = wid * 8 + i;
            const size_t gr_ = (size_t)blockRow + r;
            float4 t = *(const float4*)(Cs + r * AST + lane * 4);
            t.x += bias4.x; t.y += bias4.y; t.z += bias4.z; t.w += bias4.w;
            if (addb) {
                float4 ad = ((const float4*)addb)[gr_ * 32 + lane];
                t.x += ad.x; t.y += ad.y; t.z += ad.z; t.w += ad.w;
            }
            float4 s;
            s.x = t.x / (1.f + expf(-t.x));
            s.y = t.y / (1.f + expf(-t.y));
            s.z = t.z / (1.f + expf(-t.z));
            s.w = t.w / (1.f + expf(-t.w));
            float sum = s.x + s.y + s.z + s.w;
            float sq  = s.x * s.x + s.y * s.y + s.z * s.z + s.w * s.w;
#pragma unroll
            for (int off = 16; off; off >>= 1) {
                sum += __shfl_xor_sync(0xFFFFFFFFu, sum, off);
                sq  += __shfl_xor_sync(0xFFFFFFFFu, sq,  off);
            }
            const float mean = sum * (1.f / 128.f);
            const float var  = sq * (1.f / 128.f) - mean * mean;
            const float rstd = rsqrtf(var + EPSF);
            float4 o;
            o.x = (s.x - mean) * rstd * g4.x + b4.x;
            o.y = (s.y - mean) * rstd * g4.y + b4.y;
            o.z = (s.z - mean) * rstd * g4.z + b4.z;
            o.w = (s.w - mean) * rstd * g4.w + b4.w;
            ((float4*)C)[gr_ * 32 + lane] = o;
        }
    } else {
#pragma unroll
        for (int i = 0; i < 8; i++) {
            const int r = wid * 8 + i;
            const size_t gr_ = (size_t)blockRow + r;
            float4 t = *(const float4*)(Cs + r * AST + lane * 4);
            t.x += bias4.x; t.y += bias4.y; t.z += bias4.z; t.w += bias4.w;
            ((float4*)C)[gr_ * 32 + lane] = t;
        }
    }
}

// ---------------- k/q retention weights ----------------
__global__ void kq_kernel(const float* __restrict__ x,
                          const float* __restrict__ Wk, const float* __restrict__ Wq,
                          float* __restrict__ w0)
{
    __shared__ float4 sk4[KDIM * 32];
    __shared__ float4 sq4[KDIM * 32];
    float* sk = (float*)sk4;
    float* sqm = (float*)sq4;
    for (int idx = threadIdx.x; idx < DDIM * KDIM; idx += blockDim.x) {
        int k = idx >> 4, j = idx & 15;
        sk[j * DDIM + k] = Wk[idx];
        sqm[j * DDIM + k] = Wq[idx];
    }
    __syncthreads();

    const int lane = threadIdx.x & 31;
    int warp = (blockIdx.x * blockDim.x + threadIdx.x) >> 5;
    const int nwarps = (gridDim.x * blockDim.x) >> 5;

    for (size_t r = warp; r < (size_t)MROWS; r += nwarps) {
        const float4 xv = ((const float4*)x)[r * 32 + lane];
        float pk[KDIM], pq[KDIM];
#pragma unroll
        for (int j = 0; j < KDIM; j++) {
            float4 wk = sk4[j * 32 + lane];
            float4 wq = sq4[j * 32 + lane];
            pk[j] = xv.x * wk.x + xv.y * wk.y + xv.z * wk.z + xv.w * wk.w;
            pq[j] = xv.x * wq.x + xv.y * wq.y + xv.z * wq.z + xv.w * wq.w;
        }
#pragma unroll
        for (int off = 16; off; off >>= 1) {
#pragma unroll
            for (int j = 0; j < KDIM; j++) {
                pk[j] += __shfl_xor_sync(0xFFFFFFFFu, pk[j], off);
                pq[j] += __shfl_xor_sync(0xFFFFFFFFu, pq[j], off);
            }
        }
        if (lane == 0) {
            float s = 0.f;
#pragma unroll
            for (int j = 0; j < KDIM; j++) s += pk[j] * pq[j];
            w0[r] = s * (1.f / (float)KDIM);
        }
    }
}

// ---------------- attention output: att = LN(v * (w0+it1+it2)) ----------------
__global__ void att_ln_kernel(const float* __restrict__ v,
                              const float* __restrict__ w0, const float* __restrict__ it1,
                              const float* __restrict__ it2,
                              const float* __restrict__ g, const float* __restrict__ b,
                              float* __restrict__ out)
{
    const int lane = threadIdx.x & 31;
    int warp = (blockIdx.x * blockDim.x + threadIdx.x) >> 5;
    const int nwarps = (gridDim.x * blockDim.x) >> 5;
    const float4 g4 = ((const float4*)g)[lane];
    const float4 b4 = ((const float4*)b)[lane];

    for (size_t r = warp; r < (size_t)MROWS; r += nwarps) {
        const float w = w0[r] + it1[r] + it2[r];
        float4 s = ((const float4*)v)[r * 32 + lane];
        s.x *= w; s.y *= w; s.z *= w; s.w *= w;
        float sum = s.x + s.y + s.z + s.w;
        float sq  = s.x * s.x + s.y * s.y + s.z * s.z + s.w * s.w;
#pragma unroll
        for (int off = 16; off; off >>= 1) {
            sum += __shfl_xor_sync(0xFFFFFFFFu, sum, off);
            sq  += __shfl_xor_sync(0xFFFFFFFFu, sq,  off);
        }
        const float mean = sum * (1.f / 128.f);
        const float var  = sq * (1.f / 128.f) - mean * mean;
        const float rstd = rsqrtf(var + EPSF);
        float4 o;
        o.x = (s.x - mean) * rstd * g4.x + b4.x;
        o.y = (s.y - mean) * rstd * g4.y + b4.y;
        o.z = (s.z - mean) * rstd * g4.z + b4.z;
        o.w = (s.w - mean) * rstd * g4.w + b4.w;
        ((float4*)out)[r * 32 + lane] = o;
    }
}

// ---------------- host ----------------
extern "C" void kernel_launch(void* const* d_in, const int* in_sizes, int n_in,
                              void* d_out, int out_size)
{
    const float* x          = (const float*)d_in[0];
    const int*   ei         = (const int*)  d_in[1];
    const float* ev         = (const float*)d_in[2];
    const float* sage_W     = (const float*)d_in[3];
    const float* sage_b     = (const float*)d_in[4];
    const float* sage_aggW  = (const float*)d_in[5];
    const float* sage_ln_g  = (const float*)d_in[6];
    const float* sage_ln_b  = (const float*)d_in[7];
    const float* att_Wk     = (const float*)d_in[8];
    const float* att_Wq     = (const float*)d_in[9];
    const float* att_Wv     = (const float*)d_in[10];
    const float* att_ln_g   = (const float*)d_in[11];
    const float* att_ln_b   = (const float*)d_in[12];
    const float* lin1_W     = (const float*)d_in[13];
    const float* lin1_b     = (const float*)d_in[14];
    const float* lin2_W     = (const float*)d_in[15];
    const float* lin2_b     = (const float*)d_in[16];
    const float* ln1_g      = (const float*)d_in[17];
    const float* ln1_b      = (const float*)d_in[18];
    const float* ln2_g      = (const float*)d_in[19];
    const float* ln2_b      = (const float*)d_in[20];
    float* out = (float*)d_out;

    float *proj, *v, *agg, *sage, *att, *h, *w0, *it1, *it2;
    cudaGetSymbolAddress((void**)&proj, g_proj);
    cudaGetSymbolAddress((void**)&v,    g_v);
    cudaGetSymbolAddress((void**)&agg,  g_agg);
    cudaGetSymbolAddress((void**)&sage, g_sage);
    cudaGetSymbolAddress((void**)&att,  g_att);
    cudaGetSymbolAddress((void**)&h,    g_h);
    cudaGetSymbolAddress((void**)&w0,   g_w0);
    cudaGetSymbolAddress((void**)&it1,  g_it1);
    cudaGetSymbolAddress((void**)&it2,  g_it2);

    int *cnt, *cur, *rowstart, *ecol;
    float *eval_;
    cudaGetSymbolAddress((void**)&cnt,      g_cnt);
    cudaGetSymbolAddress((void**)&cur,      g_cur);
    cudaGetSymbolAddress((void**)&rowstart, g_rowstart);
    cudaGetSymbolAddress((void**)&ecol,     g_ecol);
    cudaGetSymbolAddress((void**)&eval_,    g_eval);

    cudaFuncSetAttribute(gemm_tc<1, 0>, cudaFuncAttributeMaxDynamicSharedMemorySize, GEMM_SMEM);
    cudaFuncSetAttribute(gemm_tc<1, 1>, cudaFuncAttributeMaxDynamicSharedMemorySize, GEMM_SMEM);
    cudaFuncSetAttribute(gemm_tc<1, 2>, cudaFuncAttributeMaxDynamicSharedMemorySize, GEMM_SMEM);
    cudaFuncSetAttribute(gemm_tc<2, 2>, cudaFuncAttributeMaxDynamicSharedMemorySize, GEMM_SMEM);

    const int gemmGrid = MROWS / 64; // 3125

    // ---- CSR build ----
    cudaMemsetAsync(cnt, 0, NNODES * sizeof(int), 0);
    cudaMemsetAsync(cur, 0, NNODES * sizeof(int), 0);
    hist_kernel<<<(EEDGES + 255) / 256, 256>>>(ei, cnt);
    scan_kernel<<<1, 1024>>>(cnt, rowstart);
    scatter_kernel<<<(EEDGES + 255) / 256, 256>>>(ei, ev, rowstart, cur, ecol, eval_);

    // proj = x @ sage_W + sage_b ; v = x @ att_Wv
    gemm_tc<1, 1><<<gemmGrid, 256, GEMM_SMEM>>>(x, nullptr, sage_W, sage_b, nullptr, nullptr, nullptr, proj);
    gemm_tc<1, 0><<<gemmGrid, 256, GEMM_SMEM>>>(x, nullptr, att_Wv, nullptr, nullptr, nullptr, nullptr, v);

    // retention base weights
    kq_kernel<<<1480, 256>>>(x, att_Wk, att_Wq, w0);

    // graph aggregation: pure gather
    spmm_gather<<<(NNODES * 4 * 32 + 255) / 256, 256>>>(rowstart, ecol, eval_, x, agg);

    // retention iterations
    ret_gather<<<(NNODES * 32 + 255) / 256, 256>>>(rowstart, ecol, eval_, w0, it1);
    ret_gather<<<(NNODES * 32 + 255) / 256, 256>>>(rowstart, ecol, eval_, it1, it2);

    // sage_out = LN(silu(proj + agg @ aggW))
    gemm_tc<1, 2><<<gemmGrid, 256, GEMM_SMEM>>>(agg, nullptr, sage_aggW, nullptr, proj,
                                                sage_ln_g, sage_ln_b, sage);
    // att_out = LN(v * weights)
    att_ln_kernel<<<1480, 256>>>(v, w0, it1, it2, att_ln_g, att_ln_b, att);

    // h = LN(silu(concat(sage,att) @ lin1_W + lin1_b))
    gemm_tc<2, 2><<<gemmGrid, 256, GEMM_SMEM>>>(sage, att, lin1_W, lin1_b, nullptr,
                                                ln1_g, ln1_b, h);
    // out = LN(silu(h @ lin2_W + lin2_b + x))
    gemm_tc<1, 2><<<gemmGrid, 256, GEMM_SMEM>>>(h, nullptr, lin2_W, lin2_b, x,
                                                ln2_g, ln2_b, out);
}